// round 4
// baseline (speedup 1.0000x reference)
#include <cuda_runtime.h>
#include <cstdint>

#define B_ROWS 16384
#define M_DIM  256
#define N_DIM  1024
#define DEPTH  16

// Scratch (allocation-free rule: __device__ globals)
__device__ float g_r[(size_t)B_ROWS * M_DIM];   // 16 MB
__device__ float g_v[(size_t)B_ROWS * N_DIM];   // 64 MB

// ---------------------------------------------------------------------------
// NT sgemm body: C[i,j] = aux[i,j] (+/-) sum_k P[i*LDP+k] * Q[j*LDQ+k]
// Block tile 128x128, K-tile 16, 256 threads, 8x8 per thread.
// All dims divide evenly (16384/128, 256/128, 1024/128, K%16==0): no bounds.
// ---------------------------------------------------------------------------
template<int LDP, int LDQ, int KTOT, bool SUB>
__device__ __forceinline__ void gemm_nt_body(const float* __restrict__ P,
                                             const float* __restrict__ Q,
                                             const float* __restrict__ aux,
                                             float* __restrict__ C,
                                             const int ldc)
{
    __shared__ float As[16][128];
    __shared__ float Bs[16][128];

    const int tid = threadIdx.x;
    const int i0  = blockIdx.y * 128;   // row tile (batch)
    const int j0  = blockIdx.x * 128;   // col tile
    const int tr  = tid >> 4;           // 0..15
    const int tc  = tid & 15;           // 0..15
    const int lk4 = (tid & 3) * 4;      // k offset of this thread's float4

    float acc[8][8];
#pragma unroll
    for (int a = 0; a < 8; ++a)
#pragma unroll
        for (int b = 0; b < 8; ++b) acc[a][b] = 0.0f;

    for (int k0 = 0; k0 < KTOT; k0 += 16) {
        // ---- global -> shared (transposed), 2 float4 per operand per thread
#pragma unroll
        for (int s = 0; s < 2; ++s) {
            const int row = (tid >> 2) + 64 * s;     // 0..127
            const float4 pv = *reinterpret_cast<const float4*>(
                &P[(size_t)(i0 + row) * LDP + k0 + lk4]);
            As[lk4 + 0][row] = pv.x;
            As[lk4 + 1][row] = pv.y;
            As[lk4 + 2][row] = pv.z;
            As[lk4 + 3][row] = pv.w;
            const float4 qv = *reinterpret_cast<const float4*>(
                &Q[(size_t)(j0 + row) * LDQ + k0 + lk4]);
            Bs[lk4 + 0][row] = qv.x;
            Bs[lk4 + 1][row] = qv.y;
            Bs[lk4 + 2][row] = qv.z;
            Bs[lk4 + 3][row] = qv.w;
        }
        __syncthreads();

#pragma unroll
        for (int k = 0; k < 16; ++k) {
            float ra[8], rb[8];
            const float4 a0 = *reinterpret_cast<const float4*>(&As[k][tr * 8]);
            const float4 a1 = *reinterpret_cast<const float4*>(&As[k][tr * 8 + 4]);
            const float4 b0 = *reinterpret_cast<const float4*>(&Bs[k][tc * 8]);
            const float4 b1 = *reinterpret_cast<const float4*>(&Bs[k][tc * 8 + 4]);
            ra[0]=a0.x; ra[1]=a0.y; ra[2]=a0.z; ra[3]=a0.w;
            ra[4]=a1.x; ra[5]=a1.y; ra[6]=a1.z; ra[7]=a1.w;
            rb[0]=b0.x; rb[1]=b0.y; rb[2]=b0.z; rb[3]=b0.w;
            rb[4]=b1.x; rb[5]=b1.y; rb[6]=b1.z; rb[7]=b1.w;
#pragma unroll
            for (int a = 0; a < 8; ++a)
#pragma unroll
                for (int b = 0; b < 8; ++b)
                    acc[a][b] = fmaf(ra[a], rb[b], acc[a][b]);
        }
        __syncthreads();
    }

    // ---- epilogue: C = aux +/- acc (vectorized)
#pragma unroll
    for (int a = 0; a < 8; ++a) {
        const int row = i0 + tr * 8 + a;
        const size_t base = (size_t)row * ldc + j0 + tc * 8;
        const float4 x0 = *reinterpret_cast<const float4*>(&aux[base]);
        const float4 x1 = *reinterpret_cast<const float4*>(&aux[base + 4]);
        float4 o0, o1;
        if (SUB) {
            o0.x = x0.x - acc[a][0]; o0.y = x0.y - acc[a][1];
            o0.z = x0.z - acc[a][2]; o0.w = x0.w - acc[a][3];
            o1.x = x1.x - acc[a][4]; o1.y = x1.y - acc[a][5];
            o1.z = x1.z - acc[a][6]; o1.w = x1.w - acc[a][7];
        } else {
            o0.x = x0.x + acc[a][0]; o0.y = x0.y + acc[a][1];
            o0.z = x0.z + acc[a][2]; o0.w = x0.w + acc[a][3];
            o1.x = x1.x + acc[a][4]; o1.y = x1.y + acc[a][5];
            o1.z = x1.z + acc[a][6]; o1.w = x1.w + acc[a][7];
        }
        *reinterpret_cast<float4*>(&C[base])     = o0;
        *reinterpret_cast<float4*>(&C[base + 4]) = o1;
    }
}

// r = x - u * A^T    (C:[B,256], K=1024)
__global__ void __launch_bounds__(256, 2)
gemm_r_kernel(const float* __restrict__ x, const float* __restrict__ A,
              const float* __restrict__ u)
{
    gemm_nt_body<N_DIM, N_DIM, N_DIM, true>(u, A, x, g_r, M_DIM);
}

// v = u + P * Wi^T   (C:[B,1024], K=256), P is g_r (or x on iter 0)
__global__ void __launch_bounds__(256, 2)
gemm_v_kernel(const float* __restrict__ P, const float* __restrict__ Wi,
              const float* __restrict__ u)
{
    gemm_nt_body<M_DIM, M_DIM, M_DIM, false>(P, Wi, u, g_v, N_DIM);
}

// ---------------------------------------------------------------------------
// Per-row exact k-th largest of |v| via 4-pass MSB radix select on fp32 bits
// (monotone for non-negative floats), then masked soft-threshold.
// One block (256 threads) per row; 4 elements per thread held in registers.
// ---------------------------------------------------------------------------
__global__ void __launch_bounds__(256)
select_kernel(const float* __restrict__ thr, const int it, const int k,
              float* __restrict__ u)
{
    const int row = blockIdx.x;
    const int tid = threadIdx.x;

    const float4 vv = *reinterpret_cast<const float4*>(
        &g_v[(size_t)row * N_DIM + tid * 4]);
    float vals[4] = { vv.x, vv.y, vv.z, vv.w };
    unsigned bits[4];
#pragma unroll
    for (int j = 0; j < 4; ++j)
        bits[j] = __float_as_uint(vals[j]) & 0x7FFFFFFFu;

    __shared__ int hist[256];
    __shared__ int sfx[256];
    __shared__ unsigned s_pref;
    __shared__ int s_k;

    unsigned prefix = 0;
    int kk = k;

#pragma unroll
    for (int pass = 0; pass < 4; ++pass) {
        const int shift = 24 - 8 * pass;
        const unsigned pmask = (pass == 0) ? 0u : (0xFFFFFFFFu << (shift + 8));

        hist[tid] = 0;
        __syncthreads();
#pragma unroll
        for (int j = 0; j < 4; ++j)
            if ((bits[j] & pmask) == prefix)
                atomicAdd(&hist[(bits[j] >> shift) & 0xFF], 1);
        __syncthreads();

        sfx[tid] = hist[tid];
        __syncthreads();
        // suffix (from-top) inclusive scan
        for (int off = 1; off < 256; off <<= 1) {
            const int add = (tid + off < 256) ? sfx[tid + off] : 0;
            __syncthreads();
            sfx[tid] += add;
            __syncthreads();
        }
        const int above = (tid < 255) ? sfx[tid + 1] : 0;
        if (sfx[tid] >= kk && above < kk) {
            s_pref = prefix | ((unsigned)tid << shift);
            s_k    = kk - above;
        }
        __syncthreads();
        prefix = s_pref;
        kk     = s_k;
        __syncthreads();
    }

    const float thresh = __uint_as_float(prefix);  // exact k-th largest |v|
    const float t = thr[it];

    float out[4];
#pragma unroll
    for (int j = 0; j < 4; ++j) {
        const float v  = vals[j];
        const float av = __uint_as_float(bits[j]);       // fabsf(v)
        const bool  m  = (av >= t) && (av >= thresh);
        float sh = fmaxf(av - t, 0.0f);
        sh = copysignf(sh, v);
        out[j] = m ? v : sh;
    }
    *reinterpret_cast<float4*>(&u[(size_t)row * N_DIM + tid * 4]) =
        make_float4(out[0], out[1], out[2], out[3]);
}

// ---------------------------------------------------------------------------
extern "C" void kernel_launch(void* const* d_in, const int* in_sizes, int n_in,
                              void* d_out, int out_size)
{
    const float* x   = (const float*)d_in[0];   // [16384, 256]
    const float* A   = (const float*)d_in[1];   // [256, 1024]
    const float* W   = (const float*)d_in[2];   // [16, 1024, 256]
    const float* thr = (const float*)d_in[3];   // [16]
    float* u = (float*)d_out;                   // [16384, 1024]

    float* r_ptr = nullptr;
    cudaGetSymbolAddress((void**)&r_ptr, g_r);  // no-op w.r.t. stream/capture

    // k = 1024 - (ceil((100-p)/100 * 1024) - 1), p = min(1.2*(i+1), 5.0)
    static const int ktab[DEPTH] = {13, 25, 37, 50, 52, 52, 52, 52,
                                    52, 52, 52, 52, 52, 52, 52, 52};

    cudaMemsetAsync(u, 0, (size_t)B_ROWS * N_DIM * sizeof(float));

    const dim3 blk(256);
    const dim3 grid_r(M_DIM / 128, B_ROWS / 128);   // (2, 128)
    const dim3 grid_v(N_DIM / 128, B_ROWS / 128);   // (8, 128)

    for (int i = 0; i < DEPTH; ++i) {
        if (i > 0)
            gemm_r_kernel<<<grid_r, blk>>>(x, A, u);
        const float* P = (i == 0) ? x : r_ptr;      // iter 0: u=0 -> r=x
        gemm_v_kernel<<<grid_v, blk>>>(P, W + (size_t)i * N_DIM * M_DIM, u);
        select_kernel<<<B_ROWS, blk>>>(thr, i, ktab[i], u);
    }
}

// round 5
// speedup vs baseline: 1.0033x; 1.0033x over previous
#include <cuda_runtime.h>
#include <cstdint>

#define B_ROWS 16384
#define M_DIM  256
#define N_DIM  1024
#define DEPTH  16

// Scratch (allocation-free rule: __device__ globals)
__device__ float g_r[(size_t)B_ROWS * M_DIM];   // 16 MB
__device__ float g_v[(size_t)B_ROWS * N_DIM];   // 64 MB

// ---------------------------------------------------------------------------
// NT sgemm body: C[i,j] = aux[i,j] (+/-) sum_k P[i*LDP+k] * Q[j*LDQ+k]
// Block tile 128x128, K-tile 16, 256 threads, 8x8 per thread.
// All dims divide evenly (16384/128, 256/128, 1024/128, K%16==0): no bounds.
// ---------------------------------------------------------------------------
template<int LDP, int LDQ, int KTOT, bool SUB>
__device__ __forceinline__ void gemm_nt_body(const float* __restrict__ P,
                                             const float* __restrict__ Q,
                                             const float* __restrict__ aux,
                                             float* __restrict__ C,
                                             const int ldc)
{
    __shared__ float As[16][128];
    __shared__ float Bs[16][128];

    const int tid = threadIdx.x;
    const int i0  = blockIdx.y * 128;   // row tile (batch)
    const int j0  = blockIdx.x * 128;   // col tile
    const int tr  = tid >> 4;           // 0..15
    const int tc  = tid & 15;           // 0..15
    const int lk4 = (tid & 3) * 4;      // k offset of this thread's float4

    float acc[8][8];
#pragma unroll
    for (int a = 0; a < 8; ++a)
#pragma unroll
        for (int b = 0; b < 8; ++b) acc[a][b] = 0.0f;

    for (int k0 = 0; k0 < KTOT; k0 += 16) {
        // ---- global -> shared (transposed), 2 float4 per operand per thread
#pragma unroll
        for (int s = 0; s < 2; ++s) {
            const int row = (tid >> 2) + 64 * s;     // 0..127
            const float4 pv = *reinterpret_cast<const float4*>(
                &P[(size_t)(i0 + row) * LDP + k0 + lk4]);
            As[lk4 + 0][row] = pv.x;
            As[lk4 + 1][row] = pv.y;
            As[lk4 + 2][row] = pv.z;
            As[lk4 + 3][row] = pv.w;
            const float4 qv = *reinterpret_cast<const float4*>(
                &Q[(size_t)(j0 + row) * LDQ + k0 + lk4]);
            Bs[lk4 + 0][row] = qv.x;
            Bs[lk4 + 1][row] = qv.y;
            Bs[lk4 + 2][row] = qv.z;
            Bs[lk4 + 3][row] = qv.w;
        }
        __syncthreads();

#pragma unroll
        for (int k = 0; k < 16; ++k) {
            float ra[8], rb[8];
            const float4 a0 = *reinterpret_cast<const float4*>(&As[k][tr * 8]);
            const float4 a1 = *reinterpret_cast<const float4*>(&As[k][tr * 8 + 4]);
            const float4 b0 = *reinterpret_cast<const float4*>(&Bs[k][tc * 8]);
            const float4 b1 = *reinterpret_cast<const float4*>(&Bs[k][tc * 8 + 4]);
            ra[0]=a0.x; ra[1]=a0.y; ra[2]=a0.z; ra[3]=a0.w;
            ra[4]=a1.x; ra[5]=a1.y; ra[6]=a1.z; ra[7]=a1.w;
            rb[0]=b0.x; rb[1]=b0.y; rb[2]=b0.z; rb[3]=b0.w;
            rb[4]=b1.x; rb[5]=b1.y; rb[6]=b1.z; rb[7]=b1.w;
#pragma unroll
            for (int a = 0; a < 8; ++a)
#pragma unroll
                for (int b = 0; b < 8; ++b)
                    acc[a][b] = fmaf(ra[a], rb[b], acc[a][b]);
        }
        __syncthreads();
    }

    // ---- epilogue: C = aux +/- acc (vectorized)
#pragma unroll
    for (int a = 0; a < 8; ++a) {
        const int row = i0 + tr * 8 + a;
        const size_t base = (size_t)row * ldc + j0 + tc * 8;
        const float4 x0 = *reinterpret_cast<const float4*>(&aux[base]);
        const float4 x1 = *reinterpret_cast<const float4*>(&aux[base + 4]);
        float4 o0, o1;
        if (SUB) {
            o0.x = x0.x - acc[a][0]; o0.y = x0.y - acc[a][1];
            o0.z = x0.z - acc[a][2]; o0.w = x0.w - acc[a][3];
            o1.x = x1.x - acc[a][4]; o1.y = x1.y - acc[a][5];
            o1.z = x1.z - acc[a][6]; o1.w = x1.w - acc[a][7];
        } else {
            o0.x = x0.x + acc[a][0]; o0.y = x0.y + acc[a][1];
            o0.z = x0.z + acc[a][2]; o0.w = x0.w + acc[a][3];
            o1.x = x1.x + acc[a][4]; o1.y = x1.y + acc[a][5];
            o1.z = x1.z + acc[a][6]; o1.w = x1.w + acc[a][7];
        }
        *reinterpret_cast<float4*>(&C[base])     = o0;
        *reinterpret_cast<float4*>(&C[base + 4]) = o1;
    }
}

// r = x - u * A^T    (C:[B,256], K=1024)
__global__ void __launch_bounds__(256, 2)
gemm_r_kernel(const float* __restrict__ x, const float* __restrict__ A,
              const float* __restrict__ u)
{
    gemm_nt_body<N_DIM, N_DIM, N_DIM, true>(u, A, x, g_r, M_DIM);
}

// v = u + P * Wi^T   (C:[B,1024], K=256), P is g_r (or x on iter 0)
__global__ void __launch_bounds__(256, 2)
gemm_v_kernel(const float* __restrict__ P, const float* __restrict__ Wi,
              const float* __restrict__ u)
{
    gemm_nt_body<M_DIM, M_DIM, M_DIM, false>(P, Wi, u, g_v, N_DIM);
}

// ---------------------------------------------------------------------------
// Per-row exact k-th largest of |v| via 4-pass MSB radix select on fp32 bits
// (monotone for non-negative floats), then masked soft-threshold.
// One block (256 threads) per row; 4 elements per thread held in registers.
// ---------------------------------------------------------------------------
__global__ void __launch_bounds__(256)
select_kernel(const float* __restrict__ thr, const int it, const int k,
              float* __restrict__ u)
{
    const int row = blockIdx.x;
    const int tid = threadIdx.x;

    const float4 vv = *reinterpret_cast<const float4*>(
        &g_v[(size_t)row * N_DIM + tid * 4]);
    float vals[4] = { vv.x, vv.y, vv.z, vv.w };
    unsigned bits[4];
#pragma unroll
    for (int j = 0; j < 4; ++j)
        bits[j] = __float_as_uint(vals[j]) & 0x7FFFFFFFu;

    __shared__ int hist[256];
    __shared__ int sfx[256];
    __shared__ unsigned s_pref;
    __shared__ int s_k;

    unsigned prefix = 0;
    int kk = k;

#pragma unroll
    for (int pass = 0; pass < 4; ++pass) {
        const int shift = 24 - 8 * pass;
        const unsigned pmask = (pass == 0) ? 0u : (0xFFFFFFFFu << (shift + 8));

        hist[tid] = 0;
        __syncthreads();
#pragma unroll
        for (int j = 0; j < 4; ++j)
            if ((bits[j] & pmask) == prefix)
                atomicAdd(&hist[(bits[j] >> shift) & 0xFF], 1);
        __syncthreads();

        sfx[tid] = hist[tid];
        __syncthreads();
        // suffix (from-top) inclusive scan
        for (int off = 1; off < 256; off <<= 1) {
            const int add = (tid + off < 256) ? sfx[tid + off] : 0;
            __syncthreads();
            sfx[tid] += add;
            __syncthreads();
        }
        const int above = (tid < 255) ? sfx[tid + 1] : 0;
        if (sfx[tid] >= kk && above < kk) {
            s_pref = prefix | ((unsigned)tid << shift);
            s_k    = kk - above;
        }
        __syncthreads();
        prefix = s_pref;
        kk     = s_k;
        __syncthreads();
    }

    const float thresh = __uint_as_float(prefix);  // exact k-th largest |v|
    const float t = thr[it];

    float out[4];
#pragma unroll
    for (int j = 0; j < 4; ++j) {
        const float v  = vals[j];
        const float av = __uint_as_float(bits[j]);       // fabsf(v)
        const bool  m  = (av >= t) && (av >= thresh);
        float sh = fmaxf(av - t, 0.0f);
        sh = copysignf(sh, v);
        out[j] = m ? v : sh;
    }
    *reinterpret_cast<float4*>(&u[(size_t)row * N_DIM + tid * 4]) =
        make_float4(out[0], out[1], out[2], out[3]);
}

// ---------------------------------------------------------------------------
extern "C" void kernel_launch(void* const* d_in, const int* in_sizes, int n_in,
                              void* d_out, int out_size)
{
    const float* x   = (const float*)d_in[0];   // [16384, 256]
    const float* A   = (const float*)d_in[1];   // [256, 1024]
    const float* W   = (const float*)d_in[2];   // [16, 1024, 256]
    const float* thr = (const float*)d_in[3];   // [16]
    float* u = (float*)d_out;                   // [16384, 1024]

    float* r_ptr = nullptr;
    cudaGetSymbolAddress((void**)&r_ptr, g_r);  // no-op w.r.t. stream/capture

    // k = 1024 - (ceil((100-p)/100 * 1024) - 1), p = min(1.2*(i+1), 5.0)
    static const int ktab[DEPTH] = {13, 25, 37, 50, 52, 52, 52, 52,
                                    52, 52, 52, 52, 52, 52, 52, 52};

    cudaMemsetAsync(u, 0, (size_t)B_ROWS * N_DIM * sizeof(float));

    const dim3 blk(256);
    const dim3 grid_r(M_DIM / 128, B_ROWS / 128);   // (2, 128)
    const dim3 grid_v(N_DIM / 128, B_ROWS / 128);   // (8, 128)

    for (int i = 0; i < DEPTH; ++i) {
        if (i > 0)
            gemm_r_kernel<<<grid_r, blk>>>(x, A, u);
        const float* P = (i == 0) ? x : r_ptr;      // iter 0: u=0 -> r=x
        gemm_v_kernel<<<grid_v, blk>>>(P, W + (size_t)i * N_DIM * M_DIM, u);
        select_kernel<<<B_ROWS, blk>>>(thr, i, ktab[i], u);
    }
}

// round 9
// speedup vs baseline: 1.4253x; 1.4207x over previous
#include <cuda_runtime.h>
#include <cstdint>

#define B_ROWS 16384
#define M_DIM  256
#define N_DIM  1024
#define DEPTH  16

// Scratch (allocation-free rule: __device__ globals)
__device__ float g_r[(size_t)B_ROWS * M_DIM];   // 16 MB
__device__ float g_v[(size_t)B_ROWS * N_DIM];   // 64 MB

// ---------------------------------------------------------------------------
// helpers
// ---------------------------------------------------------------------------
__device__ __forceinline__ uint32_t smem_u32(const void* p) {
    uint32_t a;
    asm("{ .reg .u64 t; cvta.to.shared.u64 t, %1; cvt.u32.u64 %0, t; }"
        : "=r"(a) : "l"(p));
    return a;
}

#define CP_ASYNC_16(dst, src) \
    asm volatile("cp.async.ca.shared.global [%0], [%1], 16;" \
                 :: "r"(dst), "l"(src) : "memory")
#define CP_COMMIT() asm volatile("cp.async.commit_group;" ::: "memory")

// tf32 split: hi = round-to-nearest tf32 (fp32 bit layout, low 13 mantissa
// bits zero), lo = x - hi. cvt.rna.tf32.f32 requires a .b32 destination.
__device__ __forceinline__ void tf32_split(float x, uint32_t& hi, uint32_t& lo) {
    uint32_t h;
    asm("cvt.rna.tf32.f32 %0, %1;" : "=r"(h) : "f"(x));
    hi = h;
    lo = __float_as_uint(x - __uint_as_float(h));
}

__device__ __forceinline__ void mma_tf32(float* c, const uint32_t* a,
                                         const uint32_t* b) {
    asm volatile(
        "mma.sync.aligned.m16n8k8.row.col.f32.tf32.tf32.f32 "
        "{%0,%1,%2,%3}, {%4,%5,%6,%7}, {%8,%9}, {%0,%1,%2,%3};"
        : "+f"(c[0]), "+f"(c[1]), "+f"(c[2]), "+f"(c[3])
        : "r"(a[0]), "r"(a[1]), "r"(a[2]), "r"(a[3]), "r"(b[0]), "r"(b[1]));
}

// ---------------------------------------------------------------------------
// Smem layout per stage (8192 floats = 32 KB): A tile [0,4096), B tile [4096,8192).
// Tile layout: float offset(kblk, m, klo) = kblk*512 + ((m ^ kblk) << 2) + klo
//   kblk = (k % 32) / 4 in [0,8), m in [0,128), klo = k % 4.
// cp.async writes one 16B chunk (kblk, m, 0..3): the XOR is a permutation of
// 16B slots within each kblk -> conflict-free stores; global reads are
// 128B-coalesced (8 consecutive threads cover one row's 32 floats).
// Fragment LDS: lanes hit 8 distinct XOR-permuted rows * 4 klo -> all 32 banks.
// ---------------------------------------------------------------------------
template<int KTOT>
__device__ __forceinline__ void stage_load(const float* __restrict__ P,
                                           const float* __restrict__ Q,
                                           int i0, int j0, int kt,
                                           uint32_t sbase_bytes)
{
    const int tid = threadIdx.x;
    const int k0 = kt * 32;
    const uint32_t stage = sbase_bytes + (uint32_t)((kt & 1) * 32768);
#pragma unroll
    for (int i = 0; i < 4; ++i) {
        const int c  = tid + 256 * i;       // chunk id 0..1023
        const int m  = c >> 3;
        const int kb = c & 7;
        const uint32_t da = stage + (uint32_t)((kb << 11) + ((m ^ kb) << 4));
        CP_ASYNC_16(da, &P[(size_t)(i0 + m) * KTOT + k0 + kb * 4]);
        CP_ASYNC_16(da + 16384u, &Q[(size_t)(j0 + m) * KTOT + k0 + kb * 4]);
    }
    CP_COMMIT();
}

// ---------------------------------------------------------------------------
// 3xTF32 NT GEMM via mma.sync: C[i,j] = aux[i,j] (+/-) sum_k P[i,k]*Q[j,k]
// CTA 128x128, BK=32, 256 threads, warp tile 64x32 (warp grid 2m x 4n).
// ---------------------------------------------------------------------------
template<int KTOT, bool SUB>
__device__ __forceinline__ void mma_gemm_body(const float* __restrict__ P,
                                              const float* __restrict__ Q,
                                              const float* __restrict__ aux,
                                              float* __restrict__ C,
                                              const int ldc)
{
    extern __shared__ __align__(16) float sm[];   // 2 stages x 8192 floats

    const int tid  = threadIdx.x;
    const int lane = tid & 31;
    const int w    = tid >> 5;
    const int g    = lane >> 2;
    const int t    = lane & 3;
    const int i0   = blockIdx.y * 128;
    const int j0   = blockIdx.x * 128;
    const int wm   = (w >> 2) * 64;
    const int wn   = (w & 3) * 32;

    const uint32_t sbase = smem_u32(sm);

    float acc[4][4][4];
#pragma unroll
    for (int a = 0; a < 4; ++a)
#pragma unroll
        for (int b = 0; b < 4; ++b)
#pragma unroll
            for (int c = 0; c < 4; ++c) acc[a][b][c] = 0.0f;

    constexpr int NSTAGE = KTOT / 32;
    stage_load<KTOT>(P, Q, i0, j0, 0, sbase);

#pragma unroll 1
    for (int kt = 0; kt < NSTAGE; ++kt) {
        if (kt + 1 < NSTAGE) {
            stage_load<KTOT>(P, Q, i0, j0, kt + 1, sbase);
            asm volatile("cp.async.wait_group 1;" ::: "memory");
        } else {
            asm volatile("cp.async.wait_group 0;" ::: "memory");
        }
        __syncthreads();

        const float* As = sm + (kt & 1) * 8192;
        const float* Bs = As + 4096;

#pragma unroll
        for (int ks = 0; ks < 4; ++ks) {
            const int kb0 = 2 * ks;
            const int kb1 = 2 * ks + 1;

            // A fragments: a[0]=(g,t) a[1]=(g+8,t) a[2]=(g,t+4) a[3]=(g+8,t+4)
            uint32_t ah[4][4], al[4][4];
#pragma unroll
            for (int mi = 0; mi < 4; ++mi) {
                const int m0 = wm + mi * 16 + g;
                const int m1 = m0 + 8;
                tf32_split(As[kb0 * 512 + ((m0 ^ kb0) << 2) + t], ah[mi][0], al[mi][0]);
                tf32_split(As[kb0 * 512 + ((m1 ^ kb0) << 2) + t], ah[mi][1], al[mi][1]);
                tf32_split(As[kb1 * 512 + ((m0 ^ kb1) << 2) + t], ah[mi][2], al[mi][2]);
                tf32_split(As[kb1 * 512 + ((m1 ^ kb1) << 2) + t], ah[mi][3], al[mi][3]);
            }
            // B fragments: b[0]=(k=t, n=g) b[1]=(k=t+4, n=g)
            uint32_t bh[4][2], bl[4][2];
#pragma unroll
            for (int ni = 0; ni < 4; ++ni) {
                const int n0 = wn + ni * 8 + g;
                tf32_split(Bs[kb0 * 512 + ((n0 ^ kb0) << 2) + t], bh[ni][0], bl[ni][0]);
                tf32_split(Bs[kb1 * 512 + ((n0 ^ kb1) << 2) + t], bh[ni][1], bl[ni][1]);
            }
#pragma unroll
            for (int mi = 0; mi < 4; ++mi)
#pragma unroll
                for (int ni = 0; ni < 4; ++ni) {
                    mma_tf32(acc[mi][ni], ah[mi], bh[ni]);   // hh
                    mma_tf32(acc[mi][ni], al[mi], bh[ni]);   // lh
                    mma_tf32(acc[mi][ni], ah[mi], bl[ni]);   // hl
                }
        }
        __syncthreads();
    }

    // epilogue: C = aux +/- acc
    // c0=(row g, col 2t) c1=(g,2t+1) c2=(g+8,2t) c3=(g+8,2t+1)
#pragma unroll
    for (int mi = 0; mi < 4; ++mi) {
        const int r0 = i0 + wm + mi * 16 + g;
#pragma unroll
        for (int ni = 0; ni < 4; ++ni) {
            const int col = j0 + wn + ni * 8 + 2 * t;
            const size_t o0 = (size_t)r0 * ldc + col;
            const size_t o1 = (size_t)(r0 + 8) * ldc + col;
            const float2 x0 = *reinterpret_cast<const float2*>(&aux[o0]);
            const float2 x1 = *reinterpret_cast<const float2*>(&aux[o1]);
            float2 y0, y1;
            if (SUB) {
                y0.x = x0.x - acc[mi][ni][0]; y0.y = x0.y - acc[mi][ni][1];
                y1.x = x1.x - acc[mi][ni][2]; y1.y = x1.y - acc[mi][ni][3];
            } else {
                y0.x = x0.x + acc[mi][ni][0]; y0.y = x0.y + acc[mi][ni][1];
                y1.x = x1.x + acc[mi][ni][2]; y1.y = x1.y + acc[mi][ni][3];
            }
            *reinterpret_cast<float2*>(&C[o0]) = y0;
            *reinterpret_cast<float2*>(&C[o1]) = y1;
        }
    }
}

// r = x - u * A^T    (C:[B,256], K=1024)
__global__ void __launch_bounds__(256)
mma_gemm_r(const float* __restrict__ u, const float* __restrict__ A,
           const float* __restrict__ x)
{
    mma_gemm_body<N_DIM, true>(u, A, x, g_r, M_DIM);
}

// v = u + P * Wi^T   (C:[B,1024], K=256)
__global__ void __launch_bounds__(256)
mma_gemm_v(const float* __restrict__ P, const float* __restrict__ Wi,
           const float* __restrict__ u)
{
    mma_gemm_body<M_DIM, false>(P, Wi, u, g_v, N_DIM);
}

// ---------------------------------------------------------------------------
// Per-row exact k-th largest of |v| (4-pass MSB radix select on fp32 bits),
// then masked soft-threshold. Warp-aggregated histogram atomics + single-warp
// shfl suffix scan: 3 block barriers per pass.
// ---------------------------------------------------------------------------
__global__ void __launch_bounds__(256)
select_kernel(const float* __restrict__ thr, const int it, const int k,
              float* __restrict__ u)
{
    const int row  = blockIdx.x;
    const int tid  = threadIdx.x;
    const int lane = tid & 31;

    const float4 vv = *reinterpret_cast<const float4*>(
        &g_v[(size_t)row * N_DIM + tid * 4]);
    float vals[4] = { vv.x, vv.y, vv.z, vv.w };
    unsigned bits[4];
#pragma unroll
    for (int j = 0; j < 4; ++j)
        bits[j] = __float_as_uint(vals[j]) & 0x7FFFFFFFu;

    __shared__ int hist[256];
    __shared__ unsigned s_pref;
    __shared__ int s_k;

    unsigned prefix = 0;
    int kk = k;

#pragma unroll
    for (int pass = 0; pass < 4; ++pass) {
        const int shift = 24 - 8 * pass;
        const unsigned pmask = (pass == 0) ? 0u : (0xFFFFFFFFu << (shift + 8));

        hist[tid] = 0;
        __syncthreads();

#pragma unroll
        for (int j = 0; j < 4; ++j) {
            const bool act = ((bits[j] & pmask) == prefix);
            const unsigned b = (bits[j] >> shift) & 0xFFu;
            const unsigned amask = __ballot_sync(0xFFFFFFFFu, act);
            if (act) {
                const unsigned same = __match_any_sync(amask, b);
                if (lane == (int)(__ffs(same) - 1))
                    atomicAdd(&hist[b], __popc(same));
            }
        }
        __syncthreads();

        if (tid < 32) {
            const int base = tid * 8;
            int v[8];
            int s = 0;
#pragma unroll
            for (int j = 7; j >= 0; --j) { s += hist[base + j]; v[j] = s; }
            int acc = s;                    // inclusive suffix over lanes
#pragma unroll
            for (int off = 1; off < 32; off <<= 1) {
                const int tt = __shfl_down_sync(0xFFFFFFFFu, acc, off);
                if (lane + off < 32) acc += tt;
            }
            const int above_lanes = acc - s;
#pragma unroll
            for (int j = 0; j < 8; ++j) {
                const int sfx = above_lanes + v[j];
                const int abv = above_lanes + ((j < 7) ? v[j + 1] : 0);
                if (sfx >= kk && abv < kk) {
                    s_pref = prefix | ((unsigned)(base + j) << shift);
                    s_k    = kk - abv;
                }
            }
        }
        __syncthreads();
        prefix = s_pref;
        kk     = s_k;
    }

    const float thresh = __uint_as_float(prefix);  // exact k-th largest |v|
    const float t = thr[it];

    float out[4];
#pragma unroll
    for (int j = 0; j < 4; ++j) {
        const float v  = vals[j];
        const float av = __uint_as_float(bits[j]);
        const bool  m  = (av >= t) && (av >= thresh);
        float sh = fmaxf(av - t, 0.0f);
        sh = copysignf(sh, v);
        out[j] = m ? v : sh;
    }
    *reinterpret_cast<float4*>(&u[(size_t)row * N_DIM + tid * 4]) =
        make_float4(out[0], out[1], out[2], out[3]);
}

// ---------------------------------------------------------------------------
extern "C" void kernel_launch(void* const* d_in, const int* in_sizes, int n_in,
                              void* d_out, int out_size)
{
    const float* x   = (const float*)d_in[0];   // [16384, 256]
    const float* A   = (const float*)d_in[1];   // [256, 1024]
    const float* W   = (const float*)d_in[2];   // [16, 1024, 256]
    const float* thr = (const float*)d_in[3];   // [16]
    float* u = (float*)d_out;                   // [16384, 1024]

    float* r_ptr = nullptr;
    cudaGetSymbolAddress((void**)&r_ptr, g_r);

    const int smem_bytes = 2 * 8192 * sizeof(float);   // 64 KB, double buffer
    cudaFuncSetAttribute(mma_gemm_r, cudaFuncAttributeMaxDynamicSharedMemorySize,
                         smem_bytes);
    cudaFuncSetAttribute(mma_gemm_v, cudaFuncAttributeMaxDynamicSharedMemorySize,
                         smem_bytes);

    // k = 1024 - (ceil((100-p)/100 * 1024) - 1), p = min(1.2*(i+1), 5.0)
    static const int ktab[DEPTH] = {13, 25, 37, 50, 52, 52, 52, 52,
                                    52, 52, 52, 52, 52, 52, 52, 52};

    cudaMemsetAsync(u, 0, (size_t)B_ROWS * N_DIM * sizeof(float));

    const dim3 blk(256);
    const dim3 grid_r(M_DIM / 128, B_ROWS / 128);   // (2, 128)
    const dim3 grid_v(N_DIM / 128, B_ROWS / 128);   // (8, 128)

    for (int i = 0; i < DEPTH; ++i) {
        if (i > 0)
            mma_gemm_r<<<grid_r, blk, smem_bytes>>>(u, A, x);
        const float* P = (i == 0) ? x : r_ptr;      // iter 0: u=0 -> r=x
        mma_gemm_v<<<grid_v, blk, smem_bytes>>>(P, W + (size_t)i * N_DIM * M_DIM, u);
        select_kernel<<<B_ROWS, blk>>>(thr, i, ktab[i], u);
    }
}